// round 3
// baseline (speedup 1.0000x reference)
#include <cuda_runtime.h>
#include <math.h>

#define T_TOKENS 8192
#define DM 1024
#define DF 4096
#define N_EXP 8

// ---------------- scratch (__device__ globals; no allocation allowed) -------
__device__ int   g_counts[N_EXP];
__device__ int   g_offsets[N_EXP];
__device__ int   g_tok[N_EXP * T_TOKENS];
__device__ float g_w[N_EXP * T_TOKENS];
// H activations: total routed slots = T*K = 16384 rows x 4096 cols fp32 = 256MB
__device__ float g_H[(size_t)16384 * DF];

// ---------------- helpers ---------------------------------------------------
__device__ __forceinline__ unsigned f2tf32(float f) {
    unsigned u;
    asm("cvt.rna.tf32.f32 %0, %1;" : "=r"(u) : "f"(f));
    return u;
}

__device__ __forceinline__ void mma_tf32(float c[4], const unsigned a[4], const unsigned b[2]) {
    asm volatile(
        "mma.sync.aligned.m16n8k8.row.col.f32.tf32.tf32.f32 "
        "{%0,%1,%2,%3}, {%4,%5,%6,%7}, {%8,%9}, {%0,%1,%2,%3};\n"
        : "+f"(c[0]), "+f"(c[1]), "+f"(c[2]), "+f"(c[3])
        : "r"(a[0]), "r"(a[1]), "r"(a[2]), "r"(a[3]), "r"(b[0]), "r"(b[1]));
}

__device__ __forceinline__ float gelu_exact(float v) {
    return 0.5f * v * (1.0f + erff(v * 0.70710678118654752f));
}

// ---------------- zero out + counters ---------------------------------------
__global__ void zero_kernel(float* __restrict__ out, int n4) {
    int i = blockIdx.x * blockDim.x + threadIdx.x;
    if (i < n4) reinterpret_cast<float4*>(out)[i] = make_float4(0.f, 0.f, 0.f, 0.f);
    if (i < N_EXP) g_counts[i] = 0;
}

// ---------------- gating: one warp per token --------------------------------
__global__ void gating_kernel(const float* __restrict__ x,
                              const float* __restrict__ Wg,
                              const float* __restrict__ bg,
                              float* __restrict__ logits_out,
                              int write_logits) {
    int warp = threadIdx.x >> 5;
    int lane = threadIdx.x & 31;
    int t = blockIdx.x * (blockDim.x >> 5) + warp;
    if (t >= T_TOKENS) return;

    float acc[8];
#pragma unroll
    for (int e = 0; e < 8; e++) acc[e] = 0.f;

    const float4* x4 = reinterpret_cast<const float4*>(x + (size_t)t * DM);
#pragma unroll
    for (int j = 0; j < 8; j++) {
        int idx4 = j * 32 + lane;
        float4 v = x4[idx4];
        float vv[4] = {v.x, v.y, v.z, v.w};
        int i = idx4 * 4;
#pragma unroll
        for (int c = 0; c < 4; c++) {
            const float4* w4 = reinterpret_cast<const float4*>(Wg + (size_t)(i + c) * 8);
            float4 wa = w4[0], wb = w4[1];
            acc[0] += vv[c] * wa.x; acc[1] += vv[c] * wa.y;
            acc[2] += vv[c] * wa.z; acc[3] += vv[c] * wa.w;
            acc[4] += vv[c] * wb.x; acc[5] += vv[c] * wb.y;
            acc[6] += vv[c] * wb.z; acc[7] += vv[c] * wb.w;
        }
    }
#pragma unroll
    for (int e = 0; e < 8; e++)
#pragma unroll
        for (int o = 16; o > 0; o >>= 1)
            acc[e] += __shfl_xor_sync(0xffffffffu, acc[e], o);

    if (lane == 0) {
        float lg[8];
#pragma unroll
        for (int e = 0; e < 8; e++) lg[e] = acc[e] + bg[e];
        if (write_logits) {
#pragma unroll
            for (int e = 0; e < 8; e++) logits_out[(size_t)t * 8 + e] = lg[e];
        }
        float mx = lg[0];
#pragma unroll
        for (int e = 1; e < 8; e++) mx = fmaxf(mx, lg[e]);
        float p[8], s = 0.f;
#pragma unroll
        for (int e = 0; e < 8; e++) { p[e] = expf(lg[e] - mx); s += p[e]; }
        // top-2: strict > keeps first occurrence on ties (matches jax.lax.top_k)
        int i1 = 0;
#pragma unroll
        for (int e = 1; e < 8; e++) if (p[e] > p[i1]) i1 = e;
        int i2 = -1;
#pragma unroll
        for (int e = 0; e < 8; e++) {
            if (e == i1) continue;
            if (i2 < 0 || p[e] > p[i2]) i2 = e;
        }
        float w1 = p[i1] / s, w2 = p[i2] / s;
        int pos1 = atomicAdd(&g_counts[i1], 1);
        g_tok[i1 * T_TOKENS + pos1] = t;
        g_w[i1 * T_TOKENS + pos1] = w1;
        int pos2 = atomicAdd(&g_counts[i2], 1);
        g_tok[i2 * T_TOKENS + pos2] = t;
        g_w[i2 * T_TOKENS + pos2] = w2;
    }
}

__global__ void scan_kernel() {
    if (threadIdx.x == 0 && blockIdx.x == 0) {
        int s = 0;
        for (int e = 0; e < N_EXP; e++) { g_offsets[e] = s; s += g_counts[e]; }
    }
}

// ---------------- tiled tf32 GEMM config ------------------------------------
#define BM 128
#define BN 128
#define BK 16
#define SA 20    // A smem row stride (conflict-free fragment loads)
#define SB 136   // B smem row stride (conflict-free fragment loads)

// GEMM1: H[slot, :] = gelu( X[tok, :] @ W1[e] + b1[e] )
__global__ __launch_bounds__(256) void gemm1_kernel(const float* __restrict__ x,
                                                    const float* __restrict__ W1,
                                                    const float* __restrict__ b1) {
    int e = blockIdx.z;
    int cnt = g_counts[e];
    int m0 = blockIdx.y * BM;
    if (m0 >= cnt) return;
    int n0 = blockIdx.x * BN;
    int off = g_offsets[e];
    const float* W = W1 + (size_t)e * DM * DF;

    __shared__ unsigned As[2][BM * SA];
    __shared__ unsigned Bs[2][BK * SB];

    int tid = threadIdx.x;
    // precompute gathered token per A-load row (rows tid>>2 and tid>>2 + 64)
    int tokv[2];
#pragma unroll
    for (int h = 0; h < 2; h++) {
        int r = (tid + h * 256) >> 2;
        int grow = m0 + r;
        tokv[h] = (grow < cnt) ? g_tok[e * T_TOKENS + grow] : -1;
    }

    int warp = tid >> 5, lane = tid & 31;
    int wm = (warp >> 2) * 64, wn = (warp & 3) * 32;
    int lr = lane >> 2, lc = lane & 3;

    float acc[4][4][4];
#pragma unroll
    for (int im = 0; im < 4; im++)
#pragma unroll
        for (int in_ = 0; in_ < 4; in_++)
#pragma unroll
            for (int q = 0; q < 4; q++) acc[im][in_][q] = 0.f;

    auto loadAB = [&](int buf, int k0) {
#pragma unroll
        for (int h = 0; h < 2; h++) {
            int idx = tid + h * 256;
            int r = idx >> 2, c = (idx & 3) * 4;
            float4 v = make_float4(0.f, 0.f, 0.f, 0.f);
            if (tokv[h] >= 0)
                v = *reinterpret_cast<const float4*>(x + (size_t)tokv[h] * DM + k0 + c);
            unsigned* dst = &As[buf][r * SA + c];
            dst[0] = f2tf32(v.x); dst[1] = f2tf32(v.y);
            dst[2] = f2tf32(v.z); dst[3] = f2tf32(v.w);
        }
#pragma unroll
        for (int h = 0; h < 2; h++) {
            int idx = tid + h * 256;
            int k = idx >> 5, c = (idx & 31) * 4;
            float4 v = *reinterpret_cast<const float4*>(W + (size_t)(k0 + k) * DF + n0 + c);
            unsigned* dst = &Bs[buf][k * SB + c];
            dst[0] = f2tf32(v.x); dst[1] = f2tf32(v.y);
            dst[2] = f2tf32(v.z); dst[3] = f2tf32(v.w);
        }
    };

    loadAB(0, 0);
    __syncthreads();

    const int nk = DM / BK;
    for (int kt = 0; kt < nk; kt++) {
        int buf = kt & 1;
        if (kt + 1 < nk) loadAB(buf ^ 1, (kt + 1) * BK);
#pragma unroll
        for (int ks = 0; ks < 2; ks++) {
            int kk = ks * 8;
            unsigned a[4][4], b[4][2];
#pragma unroll
            for (int im = 0; im < 4; im++) {
                int rb = wm + im * 16;
                a[im][0] = As[buf][(rb + lr) * SA + kk + lc];
                a[im][1] = As[buf][(rb + lr + 8) * SA + kk + lc];
                a[im][2] = As[buf][(rb + lr) * SA + kk + lc + 4];
                a[im][3] = As[buf][(rb + lr + 8) * SA + kk + lc + 4];
            }
#pragma unroll
            for (int in_ = 0; in_ < 4; in_++) {
                int nb = wn + in_ * 8 + lr;
                b[in_][0] = Bs[buf][(kk + lc) * SB + nb];
                b[in_][1] = Bs[buf][(kk + lc + 4) * SB + nb];
            }
#pragma unroll
            for (int im = 0; im < 4; im++)
#pragma unroll
                for (int in_ = 0; in_ < 4; in_++)
                    mma_tf32(acc[im][in_], a[im], b[in_]);
        }
        __syncthreads();
    }

    // epilogue: bias + exact gelu -> g_H
#pragma unroll
    for (int im = 0; im < 4; im++) {
#pragma unroll
        for (int in_ = 0; in_ < 4; in_++) {
            int col = n0 + wn + in_ * 8 + lc * 2;
            float bias0 = b1[(size_t)e * DF + col];
            float bias1 = b1[(size_t)e * DF + col + 1];
#pragma unroll
            for (int half = 0; half < 2; half++) {
                int r = wm + im * 16 + lr + half * 8;
                int grow = m0 + r;
                if (grow < cnt) {
                    size_t hrow = (size_t)(off + grow);
                    float v0 = acc[im][in_][half * 2 + 0] + bias0;
                    float v1 = acc[im][in_][half * 2 + 1] + bias1;
                    g_H[hrow * DF + col] = gelu_exact(v0);
                    g_H[hrow * DF + col + 1] = gelu_exact(v1);
                }
            }
        }
    }
}

// GEMM2: out[tok, :] += w * ( H[slot, :] @ W2[e] + b2[e] )
__global__ __launch_bounds__(256) void gemm2_kernel(const float* __restrict__ W2,
                                                    const float* __restrict__ b2,
                                                    float* __restrict__ out) {
    int e = blockIdx.z;
    int cnt = g_counts[e];
    int m0 = blockIdx.y * BM;
    if (m0 >= cnt) return;
    int n0 = blockIdx.x * BN;
    int off = g_offsets[e];
    const float* W = W2 + (size_t)e * DF * DM;

    __shared__ unsigned As[2][BM * SA];
    __shared__ unsigned Bs[2][BK * SB];

    int tid = threadIdx.x;
    int warp = tid >> 5, lane = tid & 31;
    int wm = (warp >> 2) * 64, wn = (warp & 3) * 32;
    int lr = lane >> 2, lc = lane & 3;

    // per-thread row validity for A loads
    int rowv[2];
#pragma unroll
    for (int h = 0; h < 2; h++) {
        int r = (tid + h * 256) >> 2;
        int grow = m0 + r;
        rowv[h] = (grow < cnt) ? (off + grow) : -1;
    }

    float acc[4][4][4];
#pragma unroll
    for (int im = 0; im < 4; im++)
#pragma unroll
        for (int in_ = 0; in_ < 4; in_++)
#pragma unroll
            for (int q = 0; q < 4; q++) acc[im][in_][q] = 0.f;

    auto loadAB = [&](int buf, int k0) {
#pragma unroll
        for (int h = 0; h < 2; h++) {
            int idx = tid + h * 256;
            int r = idx >> 2, c = (idx & 3) * 4;
            float4 v = make_float4(0.f, 0.f, 0.f, 0.f);
            if (rowv[h] >= 0)
                v = *reinterpret_cast<const float4*>(g_H + (size_t)rowv[h] * DF + k0 + c);
            unsigned* dst = &As[buf][r * SA + c];
            dst[0] = f2tf32(v.x); dst[1] = f2tf32(v.y);
            dst[2] = f2tf32(v.z); dst[3] = f2tf32(v.w);
        }
#pragma unroll
        for (int h = 0; h < 2; h++) {
            int idx = tid + h * 256;
            int k = idx >> 5, c = (idx & 31) * 4;
            float4 v = *reinterpret_cast<const float4*>(W + (size_t)(k0 + k) * DM + n0 + c);
            unsigned* dst = &Bs[buf][k * SB + c];
            dst[0] = f2tf32(v.x); dst[1] = f2tf32(v.y);
            dst[2] = f2tf32(v.z); dst[3] = f2tf32(v.w);
        }
    };

    loadAB(0, 0);
    __syncthreads();

    const int nk = DF / BK;
    for (int kt = 0; kt < nk; kt++) {
        int buf = kt & 1;
        if (kt + 1 < nk) loadAB(buf ^ 1, (kt + 1) * BK);
#pragma unroll
        for (int ks = 0; ks < 2; ks++) {
            int kk = ks * 8;
            unsigned a[4][4], b[4][2];
#pragma unroll
            for (int im = 0; im < 4; im++) {
                int rb = wm + im * 16;
                a[im][0] = As[buf][(rb + lr) * SA + kk + lc];
                a[im][1] = As[buf][(rb + lr + 8) * SA + kk + lc];
                a[im][2] = As[buf][(rb + lr) * SA + kk + lc + 4];
                a[im][3] = As[buf][(rb + lr + 8) * SA + kk + lc + 4];
            }
#pragma unroll
            for (int in_ = 0; in_ < 4; in_++) {
                int nb = wn + in_ * 8 + lr;
                b[in_][0] = Bs[buf][(kk + lc) * SB + nb];
                b[in_][1] = Bs[buf][(kk + lc + 4) * SB + nb];
            }
#pragma unroll
            for (int im = 0; im < 4; im++)
#pragma unroll
                for (int in_ = 0; in_ < 4; in_++)
                    mma_tf32(acc[im][in_], a[im], b[in_]);
        }
        __syncthreads();
    }

    // epilogue: bias + weighted deterministic atomic combine (exactly 2 adds/elem)
#pragma unroll
    for (int im = 0; im < 4; im++) {
#pragma unroll
        for (int in_ = 0; in_ < 4; in_++) {
            int col = n0 + wn + in_ * 8 + lc * 2;
            float bias0 = b2[(size_t)e * DM + col];
            float bias1 = b2[(size_t)e * DM + col + 1];
#pragma unroll
            for (int half = 0; half < 2; half++) {
                int r = wm + im * 16 + lr + half * 8;
                int grow = m0 + r;
                if (grow < cnt) {
                    int tok = g_tok[e * T_TOKENS + grow];
                    float w = g_w[e * T_TOKENS + grow];
                    float v0 = acc[im][in_][half * 2 + 0] + bias0;
                    float v1 = acc[im][in_][half * 2 + 1] + bias1;
                    atomicAdd(&out[(size_t)tok * DM + col], w * v0);
                    atomicAdd(&out[(size_t)tok * DM + col + 1], w * v1);
                }
            }
        }
    }
}

// ---------------- launch -----------------------------------------------------
extern "C" void kernel_launch(void* const* d_in, const int* in_sizes, int n_in,
                              void* d_out, int out_size) {
    const float* x  = (const float*)d_in[0];
    const float* Wg = (const float*)d_in[1];
    const float* bg = (const float*)d_in[2];
    const float* W1 = (const float*)d_in[3];
    const float* b1 = (const float*)d_in[4];
    const float* W2 = (const float*)d_in[5];
    const float* b2 = (const float*)d_in[6];
    float* out = (float*)d_out;

    int n4 = out_size / 4;
    zero_kernel<<<(n4 + 255) / 256, 256>>>(out, n4);

    const int OUT_ELEMS = T_TOKENS * DM;            // 8,388,608
    int write_logits = (out_size >= OUT_ELEMS + T_TOKENS * N_EXP);
    float* logits = out + OUT_ELEMS;
    gating_kernel<<<T_TOKENS / 8, 256>>>(x, Wg, bg, logits, write_logits);

    scan_kernel<<<1, 1>>>();

    dim3 g1(DF / BN, T_TOKENS / BM, N_EXP);
    gemm1_kernel<<<g1, 256>>>(x, W1, b1);

    dim3 g2(DM / BN, T_TOKENS / BM, N_EXP);
    gemm2_kernel<<<g2, 256>>>(W2, b2, out);
}

// round 4
// speedup vs baseline: 1.0047x; 1.0047x over previous
#include <cuda_runtime.h>
#include <math.h>

#define T_TOKENS 8192
#define DM 1024
#define DF 4096
#define N_EXP 8

// ---------------- scratch (__device__ globals; no allocation allowed) -------
__device__ int   g_counts[N_EXP];
__device__ int   g_offsets[N_EXP];
__device__ int   g_tok[N_EXP * T_TOKENS];
__device__ float g_w[N_EXP * T_TOKENS];
// H activations: total routed slots = T*K = 16384 rows x 4096 cols fp32 = 256MB
__device__ float g_H[(size_t)16384 * DF];

// ---------------- helpers ---------------------------------------------------
__device__ __forceinline__ unsigned f2tf32(float f) {
    unsigned u;
    asm("cvt.rna.tf32.f32 %0, %1;" : "=r"(u) : "f"(f));
    return u;
}

__device__ __forceinline__ void mma_tf32(float c[4], const unsigned a[4], const unsigned b[2]) {
    asm volatile(
        "mma.sync.aligned.m16n8k8.row.col.f32.tf32.tf32.f32 "
        "{%0,%1,%2,%3}, {%4,%5,%6,%7}, {%8,%9}, {%0,%1,%2,%3};\n"
        : "+f"(c[0]), "+f"(c[1]), "+f"(c[2]), "+f"(c[3])
        : "r"(a[0]), "r"(a[1]), "r"(a[2]), "r"(a[3]), "r"(b[0]), "r"(b[1]));
}

__device__ __forceinline__ float gelu_exact(float v) {
    return 0.5f * v * (1.0f + erff(v * 0.70710678118654752f));
}

// ---------------- zero out + counters ---------------------------------------
__global__ void zero_kernel(float* __restrict__ out, int n4) {
    int i = blockIdx.x * blockDim.x + threadIdx.x;
    if (i < n4) reinterpret_cast<float4*>(out)[i] = make_float4(0.f, 0.f, 0.f, 0.f);
    if (i < N_EXP) g_counts[i] = 0;
}

// ---------------- gating: one warp per token --------------------------------
__global__ void gating_kernel(const float* __restrict__ x,
                              const float* __restrict__ Wg,
                              const float* __restrict__ bg,
                              float* __restrict__ logits_out,
                              int write_logits) {
    int warp = threadIdx.x >> 5;
    int lane = threadIdx.x & 31;
    int t = blockIdx.x * (blockDim.x >> 5) + warp;
    if (t >= T_TOKENS) return;

    float acc[8];
#pragma unroll
    for (int e = 0; e < 8; e++) acc[e] = 0.f;

    const float4* x4 = reinterpret_cast<const float4*>(x + (size_t)t * DM);
#pragma unroll
    for (int j = 0; j < 8; j++) {
        int idx4 = j * 32 + lane;
        float4 v = x4[idx4];
        float vv[4] = {v.x, v.y, v.z, v.w};
        int i = idx4 * 4;
#pragma unroll
        for (int c = 0; c < 4; c++) {
            const float4* w4 = reinterpret_cast<const float4*>(Wg + (size_t)(i + c) * 8);
            float4 wa = w4[0], wb = w4[1];
            acc[0] += vv[c] * wa.x; acc[1] += vv[c] * wa.y;
            acc[2] += vv[c] * wa.z; acc[3] += vv[c] * wa.w;
            acc[4] += vv[c] * wb.x; acc[5] += vv[c] * wb.y;
            acc[6] += vv[c] * wb.z; acc[7] += vv[c] * wb.w;
        }
    }
#pragma unroll
    for (int e = 0; e < 8; e++)
#pragma unroll
        for (int o = 16; o > 0; o >>= 1)
            acc[e] += __shfl_xor_sync(0xffffffffu, acc[e], o);

    if (lane == 0) {
        float lg[8];
#pragma unroll
        for (int e = 0; e < 8; e++) lg[e] = acc[e] + bg[e];
        if (write_logits) {
#pragma unroll
            for (int e = 0; e < 8; e++) logits_out[(size_t)t * 8 + e] = lg[e];
        }
        float mx = lg[0];
#pragma unroll
        for (int e = 1; e < 8; e++) mx = fmaxf(mx, lg[e]);
        float p[8], s = 0.f;
#pragma unroll
        for (int e = 0; e < 8; e++) { p[e] = expf(lg[e] - mx); s += p[e]; }
        // top-2: strict > keeps first occurrence on ties (matches jax.lax.top_k)
        int i1 = 0;
#pragma unroll
        for (int e = 1; e < 8; e++) if (p[e] > p[i1]) i1 = e;
        int i2 = -1;
#pragma unroll
        for (int e = 0; e < 8; e++) {
            if (e == i1) continue;
            if (i2 < 0 || p[e] > p[i2]) i2 = e;
        }
        float w1 = p[i1] / s, w2 = p[i2] / s;
        int pos1 = atomicAdd(&g_counts[i1], 1);
        g_tok[i1 * T_TOKENS + pos1] = t;
        g_w[i1 * T_TOKENS + pos1] = w1;
        int pos2 = atomicAdd(&g_counts[i2], 1);
        g_tok[i2 * T_TOKENS + pos2] = t;
        g_w[i2 * T_TOKENS + pos2] = w2;
    }
}

__global__ void scan_kernel() {
    if (threadIdx.x == 0 && blockIdx.x == 0) {
        int s = 0;
        for (int e = 0; e < N_EXP; e++) { g_offsets[e] = s; s += g_counts[e]; }
    }
}

// ---------------- tiled tf32 GEMM config ------------------------------------
#define BM 128
#define BN 128
#define BK 16
#define SA 20    // A smem row stride (conflict-free fragment loads)
#define SB 136   // B smem row stride (conflict-free fragment loads)

// GEMM1: H[slot, :] = gelu( X[tok, :] @ W1[e] + b1[e] )
__global__ __launch_bounds__(256) void gemm1_kernel(const float* __restrict__ x,
                                                    const float* __restrict__ W1,
                                                    const float* __restrict__ b1) {
    int e = blockIdx.z;
    int cnt = g_counts[e];
    int m0 = blockIdx.y * BM;
    if (m0 >= cnt) return;
    int n0 = blockIdx.x * BN;
    int off = g_offsets[e];
    const float* W = W1 + (size_t)e * DM * DF;

    __shared__ unsigned As[2][BM * SA];
    __shared__ unsigned Bs[2][BK * SB];

    int tid = threadIdx.x;
    // precompute gathered token per A-load row (rows tid>>2 and tid>>2 + 64)
    int tokv[2];
#pragma unroll
    for (int h = 0; h < 2; h++) {
        int r = (tid + h * 256) >> 2;
        int grow = m0 + r;
        tokv[h] = (grow < cnt) ? g_tok[e * T_TOKENS + grow] : -1;
    }

    int warp = tid >> 5, lane = tid & 31;
    int wm = (warp >> 2) * 64, wn = (warp & 3) * 32;
    int lr = lane >> 2, lc = lane & 3;

    float acc[4][4][4];
#pragma unroll
    for (int im = 0; im < 4; im++)
#pragma unroll
        for (int in_ = 0; in_ < 4; in_++)
#pragma unroll
            for (int q = 0; q < 4; q++) acc[im][in_][q] = 0.f;

    auto loadAB = [&](int buf, int k0) {
#pragma unroll
        for (int h = 0; h < 2; h++) {
            int idx = tid + h * 256;
            int r = idx >> 2, c = (idx & 3) * 4;
            float4 v = make_float4(0.f, 0.f, 0.f, 0.f);
            if (tokv[h] >= 0)
                v = *reinterpret_cast<const float4*>(x + (size_t)tokv[h] * DM + k0 + c);
            unsigned* dst = &As[buf][r * SA + c];
            dst[0] = f2tf32(v.x); dst[1] = f2tf32(v.y);
            dst[2] = f2tf32(v.z); dst[3] = f2tf32(v.w);
        }
#pragma unroll
        for (int h = 0; h < 2; h++) {
            int idx = tid + h * 256;
            int k = idx >> 5, c = (idx & 31) * 4;
            float4 v = *reinterpret_cast<const float4*>(W + (size_t)(k0 + k) * DF + n0 + c);
            unsigned* dst = &Bs[buf][k * SB + c];
            dst[0] = f2tf32(v.x); dst[1] = f2tf32(v.y);
            dst[2] = f2tf32(v.z); dst[3] = f2tf32(v.w);
        }
    };

    loadAB(0, 0);
    __syncthreads();

    const int nk = DM / BK;
    for (int kt = 0; kt < nk; kt++) {
        int buf = kt & 1;
        if (kt + 1 < nk) loadAB(buf ^ 1, (kt + 1) * BK);
#pragma unroll
        for (int ks = 0; ks < 2; ks++) {
            int kk = ks * 8;
            unsigned a[4][4], b[4][2];
#pragma unroll
            for (int im = 0; im < 4; im++) {
                int rb = wm + im * 16;
                a[im][0] = As[buf][(rb + lr) * SA + kk + lc];
                a[im][1] = As[buf][(rb + lr + 8) * SA + kk + lc];
                a[im][2] = As[buf][(rb + lr) * SA + kk + lc + 4];
                a[im][3] = As[buf][(rb + lr + 8) * SA + kk + lc + 4];
            }
#pragma unroll
            for (int in_ = 0; in_ < 4; in_++) {
                int nb = wn + in_ * 8 + lr;
                b[in_][0] = Bs[buf][(kk + lc) * SB + nb];
                b[in_][1] = Bs[buf][(kk + lc + 4) * SB + nb];
            }
#pragma unroll
            for (int im = 0; im < 4; im++)
#pragma unroll
                for (int in_ = 0; in_ < 4; in_++)
                    mma_tf32(acc[im][in_], a[im], b[in_]);
        }
        __syncthreads();
    }

    // epilogue: bias + exact gelu -> g_H
#pragma unroll
    for (int im = 0; im < 4; im++) {
#pragma unroll
        for (int in_ = 0; in_ < 4; in_++) {
            int col = n0 + wn + in_ * 8 + lc * 2;
            float bias0 = b1[(size_t)e * DF + col];
            float bias1 = b1[(size_t)e * DF + col + 1];
#pragma unroll
            for (int half = 0; half < 2; half++) {
                int r = wm + im * 16 + lr + half * 8;
                int grow = m0 + r;
                if (grow < cnt) {
                    size_t hrow = (size_t)(off + grow);
                    float v0 = acc[im][in_][half * 2 + 0] + bias0;
                    float v1 = acc[im][in_][half * 2 + 1] + bias1;
                    g_H[hrow * DF + col] = gelu_exact(v0);
                    g_H[hrow * DF + col + 1] = gelu_exact(v1);
                }
            }
        }
    }
}

// GEMM2: out[tok, :] += w * ( H[slot, :] @ W2[e] + b2[e] )
__global__ __launch_bounds__(256) void gemm2_kernel(const float* __restrict__ W2,
                                                    const float* __restrict__ b2,
                                                    float* __restrict__ out) {
    int e = blockIdx.z;
    int cnt = g_counts[e];
    int m0 = blockIdx.y * BM;
    if (m0 >= cnt) return;
    int n0 = blockIdx.x * BN;
    int off = g_offsets[e];
    const float* W = W2 + (size_t)e * DF * DM;

    __shared__ unsigned As[2][BM * SA];
    __shared__ unsigned Bs[2][BK * SB];

    int tid = threadIdx.x;
    int warp = tid >> 5, lane = tid & 31;
    int wm = (warp >> 2) * 64, wn = (warp & 3) * 32;
    int lr = lane >> 2, lc = lane & 3;

    // per-thread row validity for A loads
    int rowv[2];
#pragma unroll
    for (int h = 0; h < 2; h++) {
        int r = (tid + h * 256) >> 2;
        int grow = m0 + r;
        rowv[h] = (grow < cnt) ? (off + grow) : -1;
    }

    float acc[4][4][4];
#pragma unroll
    for (int im = 0; im < 4; im++)
#pragma unroll
        for (int in_ = 0; in_ < 4; in_++)
#pragma unroll
            for (int q = 0; q < 4; q++) acc[im][in_][q] = 0.f;

    auto loadAB = [&](int buf, int k0) {
#pragma unroll
        for (int h = 0; h < 2; h++) {
            int idx = tid + h * 256;
            int r = idx >> 2, c = (idx & 3) * 4;
            float4 v = make_float4(0.f, 0.f, 0.f, 0.f);
            if (rowv[h] >= 0)
                v = *reinterpret_cast<const float4*>(g_H + (size_t)rowv[h] * DF + k0 + c);
            unsigned* dst = &As[buf][r * SA + c];
            dst[0] = f2tf32(v.x); dst[1] = f2tf32(v.y);
            dst[2] = f2tf32(v.z); dst[3] = f2tf32(v.w);
        }
#pragma unroll
        for (int h = 0; h < 2; h++) {
            int idx = tid + h * 256;
            int k = idx >> 5, c = (idx & 31) * 4;
            float4 v = *reinterpret_cast<const float4*>(W + (size_t)(k0 + k) * DM + n0 + c);
            unsigned* dst = &Bs[buf][k * SB + c];
            dst[0] = f2tf32(v.x); dst[1] = f2tf32(v.y);
            dst[2] = f2tf32(v.z); dst[3] = f2tf32(v.w);
        }
    };

    loadAB(0, 0);
    __syncthreads();

    const int nk = DF / BK;
    for (int kt = 0; kt < nk; kt++) {
        int buf = kt & 1;
        if (kt + 1 < nk) loadAB(buf ^ 1, (kt + 1) * BK);
#pragma unroll
        for (int ks = 0; ks < 2; ks++) {
            int kk = ks * 8;
            unsigned a[4][4], b[4][2];
#pragma unroll
            for (int im = 0; im < 4; im++) {
                int rb = wm + im * 16;
                a[im][0] = As[buf][(rb + lr) * SA + kk + lc];
                a[im][1] = As[buf][(rb + lr + 8) * SA + kk + lc];
                a[im][2] = As[buf][(rb + lr) * SA + kk + lc + 4];
                a[im][3] = As[buf][(rb + lr + 8) * SA + kk + lc + 4];
            }
#pragma unroll
            for (int in_ = 0; in_ < 4; in_++) {
                int nb = wn + in_ * 8 + lr;
                b[in_][0] = Bs[buf][(kk + lc) * SB + nb];
                b[in_][1] = Bs[buf][(kk + lc + 4) * SB + nb];
            }
#pragma unroll
            for (int im = 0; im < 4; im++)
#pragma unroll
                for (int in_ = 0; in_ < 4; in_++)
                    mma_tf32(acc[im][in_], a[im], b[in_]);
        }
        __syncthreads();
    }

    // epilogue: bias + weighted deterministic atomic combine (exactly 2 adds/elem)
#pragma unroll
    for (int im = 0; im < 4; im++) {
#pragma unroll
        for (int in_ = 0; in_ < 4; in_++) {
            int col = n0 + wn + in_ * 8 + lc * 2;
            float bias0 = b2[(size_t)e * DM + col];
            float bias1 = b2[(size_t)e * DM + col + 1];
#pragma unroll
            for (int half = 0; half < 2; half++) {
                int r = wm + im * 16 + lr + half * 8;
                int grow = m0 + r;
                if (grow < cnt) {
                    int tok = g_tok[e * T_TOKENS + grow];
                    float w = g_w[e * T_TOKENS + grow];
                    float v0 = acc[im][in_][half * 2 + 0] + bias0;
                    float v1 = acc[im][in_][half * 2 + 1] + bias1;
                    atomicAdd(&out[(size_t)tok * DM + col], w * v0);
                    atomicAdd(&out[(size_t)tok * DM + col + 1], w * v1);
                }
            }
        }
    }
}

// ---------------- launch -----------------------------------------------------
extern "C" void kernel_launch(void* const* d_in, const int* in_sizes, int n_in,
                              void* d_out, int out_size) {
    const float* x  = (const float*)d_in[0];
    const float* Wg = (const float*)d_in[1];
    const float* bg = (const float*)d_in[2];
    const float* W1 = (const float*)d_in[3];
    const float* b1 = (const float*)d_in[4];
    const float* W2 = (const float*)d_in[5];
    const float* b2 = (const float*)d_in[6];
    float* out = (float*)d_out;

    int n4 = out_size / 4;
    zero_kernel<<<(n4 + 255) / 256, 256>>>(out, n4);

    const int OUT_ELEMS = T_TOKENS * DM;            // 8,388,608
    int write_logits = (out_size >= OUT_ELEMS + T_TOKENS * N_EXP);
    float* logits = out + OUT_ELEMS;
    gating_kernel<<<T_TOKENS / 8, 256>>>(x, Wg, bg, logits, write_logits);

    scan_kernel<<<1, 1>>>();

    dim3 g1(DF / BN, T_TOKENS / BM, N_EXP);
    gemm1_kernel<<<g1, 256>>>(x, W1, b1);

    dim3 g2(DM / BN, T_TOKENS / BM, N_EXP);
    gemm2_kernel<<<g2, 256>>>(W2, b2, out);
}

// round 6
// speedup vs baseline: 1.1957x; 1.1902x over previous
#include <cuda_runtime.h>
#include <cuda_bf16.h>
#include <math.h>
#include <stdint.h>

#define T_TOKENS 8192
#define DM 1024
#define DF 4096
#define N_EXP 8

// Device-pass guard: tcgen05 only exists when compiling an arch-SPECIFIC target.
#if defined(__CUDA_ARCH__) && defined(__CUDA_ARCH_SPECIFIC__)
#define TC_DEVICE 1
#else
#define TC_DEVICE 0
#endif

// ---------------- scratch (__device__ globals) ------------------------------
__device__ int      g_counts[N_EXP];
__device__ int      g_offsets[N_EXP];
__device__ int      g_tok[N_EXP * T_TOKENS];
__device__ float    g_w[N_EXP * T_TOKENS];
// H activations. tcgen05 build: packed hi/lo bf16. fallback build: plain f32.
__device__ unsigned g_H[(size_t)16384 * DF];

// ---------------- common helpers ---------------------------------------------
__device__ __forceinline__ unsigned f2tf32(float f) {
    unsigned u;
    asm("cvt.rna.tf32.f32 %0, %1;" : "=r"(u) : "f"(f));
    return u;
}

__device__ __forceinline__ void mma_tf32(float c[4], const unsigned a[4], const unsigned b[2]) {
    asm volatile(
        "mma.sync.aligned.m16n8k8.row.col.f32.tf32.tf32.f32 "
        "{%0,%1,%2,%3}, {%4,%5,%6,%7}, {%8,%9}, {%0,%1,%2,%3};\n"
        : "+f"(c[0]), "+f"(c[1]), "+f"(c[2]), "+f"(c[3])
        : "r"(a[0]), "r"(a[1]), "r"(a[2]), "r"(a[3]), "r"(b[0]), "r"(b[1]));
}

__device__ __forceinline__ float gelu_exact(float v) {
    return 0.5f * v * (1.0f + erff(v * 0.70710678118654752f));
}

// pack two f32 -> bf16x2 (first arg -> low half, second -> high half)
__device__ __forceinline__ unsigned pack2(float lo_elem, float hi_elem) {
    unsigned r;
    asm("cvt.rn.bf16x2.f32 %0, %1, %2;" : "=r"(r) : "f"(hi_elem), "f"(lo_elem));
    return r;
}
__device__ __forceinline__ float bflo_f(unsigned u) { return __uint_as_float(u << 16); }
__device__ __forceinline__ float bfhi_f(unsigned u) { return __uint_as_float(u & 0xffff0000u); }

__device__ __forceinline__ unsigned smem_u32(const void* p) {
    unsigned a;
    asm("{ .reg .u64 t; cvta.to.shared.u64 t, %1; cvt.u32.u64 %0, t; }"
        : "=r"(a) : "l"(p));
    return a;
}

__device__ __forceinline__ unsigned elect_one() {
    unsigned p;
    asm volatile("{\n\t.reg .pred p;\n\telect.sync _|p, 0xFFFFFFFF;\n\t"
                 "selp.b32 %0, 1, 0, p;\n\t}" : "=r"(p));
    return p;
}

#define SWZ(o) ((o) ^ (((o) >> 3) & 0x70))

#define MBARRIER_INIT(addr, cnt) \
    asm volatile("mbarrier.init.shared.b64 [%0], %1;" :: "r"(addr), "r"(cnt) : "memory")

#define MBARRIER_WAIT_PARITY(addr, par) do {                                   \
    unsigned _m = (addr), _p = (par), _done;                                   \
    asm volatile("{\n\t.reg .pred p;\n\t"                                      \
        "mbarrier.try_wait.parity.acquire.cta.shared::cta.b64 p, [%1], %2;\n\t"\
        "selp.b32 %0, 1, 0, p;\n\t}" : "=r"(_done) : "r"(_m), "r"(_p) : "memory"); \
    if (!_done) {                                                              \
        asm volatile("{\n\t.reg .pred P1;\n\t"                                 \
        "WL_%=:\n\t"                                                           \
        "mbarrier.try_wait.parity.acquire.cta.shared::cta.b64 P1, [%0], %1, 0x989680;\n\t" \
        "@P1 bra.uni WD_%=;\n\t"                                               \
        "bra.uni WL_%=;\n\t"                                                   \
        "WD_%=:\n\t}" :: "r"(_m), "r"(_p) : "memory");                         \
    }                                                                          \
} while (0)

// ---------------- zero + gating + scan (verified) ----------------------------
__global__ void zero_kernel(float* __restrict__ out, int n4) {
    int i = blockIdx.x * blockDim.x + threadIdx.x;
    if (i < n4) reinterpret_cast<float4*>(out)[i] = make_float4(0.f, 0.f, 0.f, 0.f);
    if (i < N_EXP) g_counts[i] = 0;
}

__global__ void gating_kernel(const float* __restrict__ x,
                              const float* __restrict__ Wg,
                              const float* __restrict__ bg,
                              float* __restrict__ logits_out,
                              int write_logits) {
    int warp = threadIdx.x >> 5;
    int lane = threadIdx.x & 31;
    int t = blockIdx.x * (blockDim.x >> 5) + warp;
    if (t >= T_TOKENS) return;

    float acc[8];
#pragma unroll
    for (int e = 0; e < 8; e++) acc[e] = 0.f;

    const float4* x4 = reinterpret_cast<const float4*>(x + (size_t)t * DM);
#pragma unroll
    for (int j = 0; j < 8; j++) {
        int idx4 = j * 32 + lane;
        float4 v = x4[idx4];
        float vv[4] = {v.x, v.y, v.z, v.w};
        int i = idx4 * 4;
#pragma unroll
        for (int c = 0; c < 4; c++) {
            const float4* w4 = reinterpret_cast<const float4*>(Wg + (size_t)(i + c) * 8);
            float4 wa = w4[0], wb = w4[1];
            acc[0] += vv[c] * wa.x; acc[1] += vv[c] * wa.y;
            acc[2] += vv[c] * wa.z; acc[3] += vv[c] * wa.w;
            acc[4] += vv[c] * wb.x; acc[5] += vv[c] * wb.y;
            acc[6] += vv[c] * wb.z; acc[7] += vv[c] * wb.w;
        }
    }
#pragma unroll
    for (int e = 0; e < 8; e++)
#pragma unroll
        for (int o = 16; o > 0; o >>= 1)
            acc[e] += __shfl_xor_sync(0xffffffffu, acc[e], o);

    if (lane == 0) {
        float lg[8];
#pragma unroll
        for (int e = 0; e < 8; e++) lg[e] = acc[e] + bg[e];
        if (write_logits) {
#pragma unroll
            for (int e = 0; e < 8; e++) logits_out[(size_t)t * 8 + e] = lg[e];
        }
        float mx = lg[0];
#pragma unroll
        for (int e = 1; e < 8; e++) mx = fmaxf(mx, lg[e]);
        float p[8], s = 0.f;
#pragma unroll
        for (int e = 0; e < 8; e++) { p[e] = expf(lg[e] - mx); s += p[e]; }
        int i1 = 0;
#pragma unroll
        for (int e = 1; e < 8; e++) if (p[e] > p[i1]) i1 = e;
        int i2 = -1;
#pragma unroll
        for (int e = 0; e < 8; e++) {
            if (e == i1) continue;
            if (i2 < 0 || p[e] > p[i2]) i2 = e;
        }
        float w1 = p[i1] / s, w2 = p[i2] / s;
        int pos1 = atomicAdd(&g_counts[i1], 1);
        g_tok[i1 * T_TOKENS + pos1] = t;
        g_w[i1 * T_TOKENS + pos1] = w1;
        int pos2 = atomicAdd(&g_counts[i2], 1);
        g_tok[i2 * T_TOKENS + pos2] = t;
        g_w[i2 * T_TOKENS + pos2] = w2;
    }
}

__global__ void scan_kernel() {
    if (threadIdx.x == 0 && blockIdx.x == 0) {
        int s = 0;
        for (int e = 0; e < N_EXP; e++) { g_offsets[e] = s; s += g_counts[e]; }
    }
}

// ============================================================================
// PATH A: tcgen05 grouped GEMM (compiled only for arch-specific sm_103a)
// ============================================================================
#define TCGEN05_ALLOC(sm_addr, n) \
    asm volatile("tcgen05.alloc.cta_group::1.sync.aligned.shared::cta.b32 [%0], %1;" \
                 :: "r"(sm_addr), "r"((unsigned)(n)) : "memory")
#define TCGEN05_DEALLOC(tm, n) \
    asm volatile("tcgen05.dealloc.cta_group::1.sync.aligned.b32 %0, %1;" \
                 :: "r"(tm), "r"((unsigned)(n)))
#define TCGEN05_RELINQ() \
    asm volatile("tcgen05.relinquish_alloc_permit.cta_group::1.sync.aligned;")
#define TCGEN05_COMMIT(mbar) \
    asm volatile("tcgen05.commit.cta_group::1.mbarrier::arrive::one.shared::cluster.b64 [%0];" \
                 :: "r"(mbar) : "memory")
#define TCGEN05_FENCE_AFTER() \
    asm volatile("tcgen05.fence::after_thread_sync;" ::: "memory")
#define TCGEN05_FENCE_BEFORE() \
    asm volatile("tcgen05.fence::before_thread_sync;" ::: "memory")
#define TCGEN05_WAIT_LD() \
    asm volatile("tcgen05.wait::ld.sync.aligned;" ::: "memory")
#define FENCE_PROXY_ASYNC() \
    asm volatile("fence.proxy.async.shared::cta;" ::: "memory")

#define TCGEN05_LD_X32(r, tm)                                                  \
    asm volatile("tcgen05.ld.sync.aligned.32x32b.x32.b32 "                     \
        "{%0, %1, %2, %3, %4, %5, %6, %7, "                                    \
        " %8, %9, %10, %11, %12, %13, %14, %15, "                              \
        " %16, %17, %18, %19, %20, %21, %22, %23, "                            \
        " %24, %25, %26, %27, %28, %29, %30, %31}, [%32];"                     \
        : "=r"((r)[0]),  "=r"((r)[1]),  "=r"((r)[2]),  "=r"((r)[3]),           \
          "=r"((r)[4]),  "=r"((r)[5]),  "=r"((r)[6]),  "=r"((r)[7]),           \
          "=r"((r)[8]),  "=r"((r)[9]),  "=r"((r)[10]), "=r"((r)[11]),          \
          "=r"((r)[12]), "=r"((r)[13]), "=r"((r)[14]), "=r"((r)[15]),          \
          "=r"((r)[16]), "=r"((r)[17]), "=r"((r)[18]), "=r"((r)[19]),          \
          "=r"((r)[20]), "=r"((r)[21]), "=r"((r)[22]), "=r"((r)[23]),          \
          "=r"((r)[24]), "=r"((r)[25]), "=r"((r)[26]), "=r"((r)[27]),          \
          "=r"((r)[28]), "=r"((r)[29]), "=r"((r)[30]), "=r"((r)[31])           \
        : "r"(tm))

#if TC_DEVICE
__device__ __forceinline__ void mma_f16_ss(unsigned d, uint64_t a, uint64_t b,
                                           unsigned idesc, unsigned en) {
    asm volatile("{\n\t.reg .pred p;\n\tsetp.ne.u32 p, %4, 0;\n\t"
                 "tcgen05.mma.cta_group::1.kind::f16 [%0], %1, %2, %3, {%5,%5,%5,%5}, p;\n\t}"
                 :: "r"(d), "l"(a), "l"(b), "r"(idesc), "r"(en), "r"(0u)
                 : "memory");
}
#endif

__device__ __forceinline__ uint64_t make_desc(unsigned addr) {
    const uint64_t BASE = (2ull << 61) | (1ull << 46) | (64ull << 32) | (1ull << 16);
    return BASE | ((uint64_t)(addr >> 4) & 0x3FFF);
}

// idesc: dtype=F32(1<<4), atype=BF16(1<<7), btype=BF16(1<<10), N=128, M=128
#define IDESC 0x08200490u

#define CHUNK_K   64
#define ABYTES    16384
#define BUFBYTES  65536
#define TC_SMEM_BYTES (2048 + 2 * BUFBYTES)

template<int IS_G1>
__global__ __launch_bounds__(256, 1) void moe_gemm_tc(
    const float* __restrict__ x,
    const float* __restrict__ W,
    const float* __restrict__ bias,
    float* __restrict__ out)
{
#if TC_DEVICE
    constexpr int KTOT = IS_G1 ? DM : DF;
    constexpr int NTOT = IS_G1 ? DF : DM;
    constexpr int NC = KTOT / CHUNK_K;

    int e = blockIdx.z;
    int cnt = g_counts[e];
    int m0 = blockIdx.y * 128;
    if (m0 >= cnt) return;
    int n0 = blockIdx.x * 128;
    int off = g_offsets[e];
    const float* Wexp = W + (size_t)e * KTOT * NTOT;

    extern __shared__ char smem_c[];
    unsigned s0 = smem_u32(smem_c);
    unsigned s_tile = (s0 + 1024 + 1023) & ~1023u;
    char* tile_c = smem_c + (s_tile - s0);

    int tid = threadIdx.x;
    int wid = tid >> 5;
    int lane = tid & 31;

    if (wid == 0) TCGEN05_ALLOC(s0, 128);
    else TCGEN05_RELINQ();
    if (tid == 0) {
        MBARRIER_INIT(s0 + 8, 1);
        MBARRIER_INIT(s0 + 16, 1);
    }
    __syncthreads();
    unsigned tmem;
    asm volatile("ld.shared.b32 %0, [%1];" : "=r"(tmem) : "r"(s0));

    int rowid[8];
#pragma unroll
    for (int it = 0; it < 8; it++) {
        int row = (tid >> 4) + it * 16;
        int grow = m0 + row;
        if (grow >= cnt) rowid[it] = -1;
        else rowid[it] = IS_G1 ? g_tok[e * T_TOKENS + grow] : (off + grow);
    }

    uint64_t dAH[2], dAL[2], dBH[2], dBL[2];
#pragma unroll
    for (int b = 0; b < 2; b++) {
        unsigned base = s_tile + b * BUFBYTES;
        dAH[b] = make_desc(base);
        dAL[b] = make_desc(base + ABYTES);
        dBH[b] = make_desc(base + 2 * ABYTES);
        dBL[b] = make_desc(base + 3 * ABYTES);
    }

    int ph[2] = {0, 0};

    for (int c = 0; c < NC; c++) {
        int buf = c & 1;
        if (c >= 2) {
            MBARRIER_WAIT_PARITY(s0 + 8 + buf * 8, ph[buf]);
            ph[buf] ^= 1;
        }
        int k0 = c * CHUNK_K;
        char* ah = tile_c + buf * BUFBYTES;
        char* al = ah + ABYTES;
        char* bh = ah + 2 * ABYTES;
        char* bl = ah + 3 * ABYTES;

        // ---- A fill: 128 rows x 64 k (fp32 -> hi/lo bf16) ----
#pragma unroll
        for (int it = 0; it < 8; it++) {
            int idx = tid + it * 256;
            int kq = idx & 15;
            int row = idx >> 4;
            unsigned h01, h23, l01, l23;
            if (IS_G1) {
                float4 v = make_float4(0.f, 0.f, 0.f, 0.f);
                if (rowid[it] >= 0)
                    v = *reinterpret_cast<const float4*>(
                        x + (size_t)rowid[it] * DM + k0 + kq * 4);
                h01 = pack2(v.x, v.y);
                h23 = pack2(v.z, v.w);
                l01 = pack2(v.x - bflo_f(h01), v.y - bfhi_f(h01));
                l23 = pack2(v.z - bflo_f(h23), v.w - bfhi_f(h23));
            } else {
                uint4 u = make_uint4(0, 0, 0, 0);
                if (rowid[it] >= 0)
                    u = *reinterpret_cast<const uint4*>(
                        g_H + (size_t)rowid[it] * DF + k0 + kq * 4);
                h01 = __byte_perm(u.x, u.y, 0x7632);
                l01 = __byte_perm(u.x, u.y, 0x5410);
                h23 = __byte_perm(u.z, u.w, 0x7632);
                l23 = __byte_perm(u.z, u.w, 0x5410);
            }
            unsigned o = SWZ((unsigned)(row * 128 + kq * 8));
            *reinterpret_cast<uint2*>(ah + o) = make_uint2(h01, h23);
            *reinterpret_cast<uint2*>(al + o) = make_uint2(l01, l23);
        }

        // ---- B fill: B[n][k] = W[k0+k][n0+n]; 128 n x 64 k ----
        const float* Wk0 = Wexp + (size_t)k0 * NTOT + n0;
#pragma unroll
        for (int it = 0; it < 4; it++) {
            int idx = tid + it * 256;
            int kp = idx & 31;
            int nq = idx >> 5;
            const float* p0 = Wk0 + (size_t)(2 * kp) * NTOT + nq * 4;
            float4 v0 = *reinterpret_cast<const float4*>(p0);
            float4 v1 = *reinterpret_cast<const float4*>(p0 + NTOT);
            float a0[4] = {v0.x, v0.y, v0.z, v0.w};
            float a1[4] = {v1.x, v1.y, v1.z, v1.w};
#pragma unroll
            for (int j = 0; j < 4; j++) {
                int n = nq * 4 + j;
                unsigned o = SWZ((unsigned)(n * 128 + kp * 4));
                unsigned h2 = pack2(a0[j], a1[j]);
                unsigned l2 = pack2(a0[j] - bflo_f(h2), a1[j] - bfhi_f(h2));
                *reinterpret_cast<unsigned*>(bh + o) = h2;
                *reinterpret_cast<unsigned*>(bl + o) = l2;
            }
        }

        __syncthreads();

        if (tid < 32 && elect_one()) {
            FENCE_PROXY_ASYNC();
            uint64_t ta[3] = {dAH[buf], dAH[buf], dAL[buf]};
            uint64_t tb[3] = {dBH[buf], dBL[buf], dBH[buf]};
#pragma unroll
            for (int t = 0; t < 3; t++) {
#pragma unroll
                for (int ks = 0; ks < 4; ks++) {
                    unsigned en = (c == 0 && t == 0 && ks == 0) ? 0u : 1u;
                    mma_f16_ss(tmem, ta[t] + ks * 2, tb[t] + ks * 2, IDESC, en);
                }
            }
            TCGEN05_COMMIT(s0 + 8 + buf * 8);
        }
    }

    {
        int lb = (NC - 1) & 1;
        MBARRIER_WAIT_PARITY(s0 + 8 + lb * 8, ph[lb]);
    }
    TCGEN05_FENCE_AFTER();

    // ---- epilogue: TMEM -> smem stage (pitch 129 f32) -> global ----
    float* stage = reinterpret_cast<float*>(tile_c);
    if (wid < 4) {
        int rbase = (wid * 32 + lane) * 129;
#pragma unroll
        for (int g = 0; g < 4; g++) {
            unsigned r[32];
            TCGEN05_LD_X32(r, tmem + g * 32);
            TCGEN05_WAIT_LD();
#pragma unroll
            for (int q = 0; q < 32; q++)
                stage[rbase + g * 32 + q] = __uint_as_float(r[q]);
        }
        TCGEN05_FENCE_BEFORE();
    }
    __syncthreads();

    {
        int colb = lane * 4;
        float b0 = bias[(size_t)e * NTOT + n0 + colb + 0];
        float b1v = bias[(size_t)e * NTOT + n0 + colb + 1];
        float b2v = bias[(size_t)e * NTOT + n0 + colb + 2];
        float b3 = bias[(size_t)e * NTOT + n0 + colb + 3];
#pragma unroll 4
        for (int rr = 0; rr < 16; rr++) {
            int row = wid * 16 + rr;
            int grow = m0 + row;
            if (grow >= cnt) continue;
            float v0 = stage[row * 129 + colb + 0] + b0;
            float v1 = stage[row * 129 + colb + 1] + b1v;
            float v2 = stage[row * 129 + colb + 2] + b2v;
            float v3 = stage[row * 129 + colb + 3] + b3;
            if (IS_G1) {
                float a0 = gelu_exact(v0), a1 = gelu_exact(v1);
                float a2 = gelu_exact(v2), a3 = gelu_exact(v3);
                unsigned h01 = pack2(a0, a1);
                unsigned l01 = pack2(a0 - bflo_f(h01), a1 - bfhi_f(h01));
                unsigned h23 = pack2(a2, a3);
                unsigned l23 = pack2(a2 - bflo_f(h23), a3 - bfhi_f(h23));
                uint4 pk;
                pk.x = __byte_perm(l01, h01, 0x5410);
                pk.y = __byte_perm(l01, h01, 0x7632);
                pk.z = __byte_perm(l23, h23, 0x5410);
                pk.w = __byte_perm(l23, h23, 0x7632);
                size_t hrow = (size_t)(off + grow);
                *reinterpret_cast<uint4*>(g_H + hrow * DF + n0 + colb) = pk;
            } else {
                int tok = g_tok[e * T_TOKENS + grow];
                float w = g_w[e * T_TOKENS + grow];
                float* op = out + (size_t)tok * DM + n0 + colb;
                atomicAdd(op + 0, w * v0);
                atomicAdd(op + 1, w * v1);
                atomicAdd(op + 2, w * v2);
                atomicAdd(op + 3, w * v3);
            }
        }
    }

    if (wid == 0) TCGEN05_DEALLOC(tmem, 128);
#endif  // TC_DEVICE
}

// ============================================================================
// PATH B: mma.sync tf32 fallback (round-4 verified math, LDG/MMA/STS pipelined)
// ============================================================================
#define BM 128
#define BN 128
#define BK 16
#define SA 20
#define SB 136

__global__ __launch_bounds__(256) void gemm1_fb(const float* __restrict__ x,
                                                const float* __restrict__ W1,
                                                const float* __restrict__ b1) {
    int e = blockIdx.z;
    int cnt = g_counts[e];
    int m0 = blockIdx.y * BM;
    if (m0 >= cnt) return;
    int n0 = blockIdx.x * BN;
    int off = g_offsets[e];
    const float* W = W1 + (size_t)e * DM * DF;
    float* gH = reinterpret_cast<float*>(g_H);

    __shared__ unsigned As[2][BM * SA];
    __shared__ unsigned Bs[2][BK * SB];

    int tid = threadIdx.x;
    int tokv[2];
#pragma unroll
    for (int h = 0; h < 2; h++) {
        int r = (tid + h * 256) >> 2;
        int grow = m0 + r;
        tokv[h] = (grow < cnt) ? g_tok[e * T_TOKENS + grow] : -1;
    }

    int warp = tid >> 5, lane = tid & 31;
    int wm = (warp >> 2) * 64, wn = (warp & 3) * 32;
    int lr = lane >> 2, lc = lane & 3;

    float acc[4][4][4];
#pragma unroll
    for (int im = 0; im < 4; im++)
#pragma unroll
        for (int in_ = 0; in_ < 4; in_++)
#pragma unroll
            for (int q = 0; q < 4; q++) acc[im][in_][q] = 0.f;

    float4 va[2], vb[2];
    auto ldg = [&](int k0) {
#pragma unroll
        for (int h = 0; h < 2; h++) {
            int idx = tid + h * 256;
            int c = (idx & 3) * 4;
            va[h] = make_float4(0.f, 0.f, 0.f, 0.f);
            if (tokv[h] >= 0)
                va[h] = *reinterpret_cast<const float4*>(x + (size_t)tokv[h] * DM + k0 + c);
        }
#pragma unroll
        for (int h = 0; h < 2; h++) {
            int idx = tid + h * 256;
            int k = idx >> 5, c = (idx & 31) * 4;
            vb[h] = *reinterpret_cast<const float4*>(W + (size_t)(k0 + k) * DF + n0 + c);
        }
    };
    auto sts = [&](int buf) {
#pragma unroll
        for (int h = 0; h < 2; h++) {
            int idx = tid + h * 256;
            int r = idx >> 2, c = (idx & 3) * 4;
            unsigned* dst = &As[buf][r * SA + c];
            dst[0] = f2tf32(va[h].x); dst[1] = f2tf32(va[h].y);
            dst[2] = f2tf32(va[h].z); dst[3] = f2tf32(va[h].w);
        }
#pragma unroll
        for (int h = 0; h < 2; h++) {
            int idx = tid + h * 256;
            int k = idx >> 5, c = (idx & 31) * 4;
            unsigned* dst = &Bs[buf][k * SB + c];
            dst[0] = f2tf32(vb[h].x); dst[1] = f2tf32(vb[h].y);
            dst[2] = f2tf32(vb[h].z); dst[3] = f2tf32(vb[h].w);
        }
    };

    ldg(0);
    sts(0);
    __syncthreads();

    const int nk = DM / BK;
    for (int kt = 0; kt < nk; kt++) {
        int buf = kt & 1;
        if (kt + 1 < nk) ldg((kt + 1) * BK);
#pragma unroll
        for (int ks = 0; ks < 2; ks++) {
            int kk = ks * 8;
            unsigned a[4][4], b[4][2];
#pragma unroll
            for (int im = 0; im < 4; im++) {
                int rb = wm + im * 16;
                a[im][0] = As[buf][(rb + lr) * SA + kk + lc];
                a[im][1] = As[buf][(rb + lr + 8) * SA + kk + lc];
                a[im][2] = As[buf][(rb + lr) * SA + kk + lc + 4];
                a[im][3] = As[buf][(rb + lr + 8) * SA + kk + lc + 4];
            }
#pragma unroll
            for (int in_ = 0; in_ < 4; in_++) {
                int nb = wn + in_ * 8 + lr;
                b[in_][0] = Bs[buf][(kk + lc) * SB + nb];
                b[in_][1] = Bs[buf][(kk + lc + 4) * SB + nb];
            }
#pragma unroll
            for (int im = 0; im < 4; im++)
#pragma unroll
                for (int in_ = 0; in_ < 4; in_++)
                    mma_tf32(acc[im][in_], a[im], b[in_]);
        }
        if (kt + 1 < nk) sts(buf ^ 1);
        __syncthreads();
    }

#pragma unroll
    for (int im = 0; im < 4; im++) {
#pragma unroll
        for (int in_ = 0; in_ < 4; in_++) {
            int col = n0 + wn + in_ * 8 + lc * 2;
            float bias0 = b1[(size_t)e * DF + col];
            float bias1 = b1[(size_t)e * DF + col + 1];
#pragma unroll
            for (int half = 0; half < 2; half++) {
                int r = wm + im * 16 + lr + half * 8;
                int grow = m0 + r;
                if (grow < cnt) {
                    size_t hrow = (size_t)(off + grow);
                    float v0 = acc[im][in_][half * 2 + 0] + bias0;
                    float v1 = acc[im][in_][half * 2 + 1] + bias1;
                    gH[hrow * DF + col] = gelu_exact(v0);
                    gH[hrow * DF + col + 1] = gelu_exact(v1);
                }
            }
        }
    }
}

__global__ __launch_bounds__(256) void gemm2_fb(const float* __restrict__ W2,
                                                const float* __restrict__ b2,
                                                float* __restrict__ out) {
    int e = blockIdx.z;
    int cnt = g_counts[e];
    int m0 = blockIdx.y * BM;
    if (m0 >= cnt) return;
    int n0 = blockIdx.x * BN;
    int off = g_offsets[e];
    const float* W = W2 + (size_t)e * DF * DM;
    const float* gH = reinterpret_cast<const float*>(g_H);

    __shared__ unsigned As[2][BM * SA];
    __shared__ unsigned Bs[2][BK * SB];

    int tid = threadIdx.x;
    int warp = tid >> 5, lane = tid & 31;
    int wm = (warp >> 2) * 64, wn = (warp & 3) * 32;
    int lr = lane >> 2, lc = lane & 3;

    int rowv[2];
#pragma unroll
    for (int h = 0; h < 2; h++) {
        int r = (tid + h * 256) >> 2;
        int grow = m0 + r;
        rowv[h] = (grow < cnt) ? (off + grow) : -1;
    }

    float acc[4][4][4];
#pragma unroll
    for (int im = 0; im < 4; im++)
#pragma unroll
        for (int in_ = 0; in_ < 4; in_++)
#pragma unroll
            for (int q = 0; q < 4; q++) acc[im][in_][q] = 0.f;

    float4 va[2], vb[2];
    auto ldg = [&](int k0) {
#pragma unroll
        for (int h = 0; h < 2; h++) {
            int idx = tid + h * 256;
            int c = (idx & 3) * 4;
            va[h] = make_float4(0.f, 0.f, 0.f, 0.f);
            if (rowv[h] >= 0)
                va[h] = *reinterpret_cast<const float4*>(gH + (size_t)rowv[h] * DF + k0 + c);
        }
#pragma unroll
        for (int h = 0; h < 2; h++) {
            int idx = tid + h * 256;
            int k = idx >> 5, c = (idx & 31) * 4;
            vb[h] = *reinterpret_cast<const float4*>(W + (size_t)(k0 + k) * DM + n0 + c);
        }
    };
    auto sts = [&](int buf) {
#pragma unroll
        for (int h = 0; h < 2; h++) {
            int idx = tid + h * 256;
            int r = idx >> 2, c = (idx & 3) * 4;
            unsigned* dst = &As[buf][r * SA + c];
            dst[0] = f2tf32(va[h].x); dst[1] = f2tf32(va[h].y);
            dst[2] = f2tf32(va[h].z); dst[3] = f2tf32(va[h].w);
        }
#pragma unroll
        for (int h = 0; h < 2; h++) {
            int idx = tid + h * 256;
            int k = idx >> 5, c = (idx & 31) * 4;
            unsigned* dst = &Bs[buf][k * SB + c];
            dst[0] = f2tf32(vb[h].x); dst[1] = f2tf32(vb[h].y);
            dst[2] = f2tf32(vb[h].z); dst[3] = f2tf32(vb[h].w);
        }
    };

    ldg(0);
    sts(0);
    __syncthreads();

    const int nk = DF / BK;
    for (int kt = 0; kt < nk; kt++) {
        int buf = kt & 1;
        if (kt + 1 < nk) ldg((kt + 1) * BK);
#pragma unroll
        for (int ks = 0; ks < 2; ks++) {
            int kk = ks * 8;
            unsigned a[4][4], b[4][2];
#pragma unroll
            for (int im = 0; im < 4; im++) {
                int rb = wm + im * 16;
                a[im][0] = As[buf][(rb + lr) * SA + kk + lc];
                a[im][1] = As[buf][(rb + lr + 8) * SA + kk + lc];
                a[im][2] = As[buf][(rb + lr) * SA + kk + lc + 4];
                a[im][3] = As[buf][(rb + lr + 8) * SA + kk + lc + 4];
            }
#pragma unroll
            for (int in_ = 0; in_ < 4; in_++) {
                int nb = wn + in_ * 8 + lr;
                b[in_][0] = Bs[buf][(kk + lc) * SB + nb];
                b[in_][1] = Bs[buf][(kk + lc + 4) * SB + nb];
            }
#pragma unroll
            for (int im = 0; im < 4; im++)
#pragma unroll
                for (int in_ = 0; in_ < 4; in_++)
                    mma_tf32(acc[im][in_], a[im], b[in_]);
        }
        if (kt + 1 < nk) sts(buf ^ 1);
        __syncthreads();
    }

#pragma unroll
    for (int im = 0; im < 4; im++) {
#pragma unroll
        for (int in_ = 0; in_ < 4; in_++) {
            int col = n0 + wn + in_ * 8 + lc * 2;
            float bias0 = b2[(size_t)e * DM + col];
            float bias1 = b2[(size_t)e * DM + col + 1];
#pragma unroll
            for (int half = 0; half < 2; half++) {
                int r = wm + im * 16 + lr + half * 8;
                int grow = m0 + r;
                if (grow < cnt) {
                    int tok = g_tok[e * T_TOKENS + grow];
                    float w = g_w[e * T_TOKENS + grow];
                    float v0 = acc[im][in_][half * 2 + 0] + bias0;
                    float v1 = acc[im][in_][half * 2 + 1] + bias1;
                    atomicAdd(&out[(size_t)tok * DM + col], w * v0);
                    atomicAdd(&out[(size_t)tok * DM + col + 1], w * v1);
                }
            }
        }
    }
}

// ---------------- launch -----------------------------------------------------
extern "C" void kernel_launch(void* const* d_in, const int* in_sizes, int n_in,
                              void* d_out, int out_size) {
    const float* x  = (const float*)d_in[0];
    const float* Wg = (const float*)d_in[1];
    const float* bg = (const float*)d_in[2];
    const float* W1 = (const float*)d_in[3];
    const float* b1 = (const float*)d_in[4];
    const float* W2 = (const float*)d_in[5];
    const float* b2 = (const float*)d_in[6];
    float* out = (float*)d_out;

    int n4 = out_size / 4;
    zero_kernel<<<(n4 + 255) / 256, 256>>>(out, n4);

    const int OUT_ELEMS = T_TOKENS * DM;
    int write_logits = (out_size >= OUT_ELEMS + T_TOKENS * N_EXP);
    float* logits = out + OUT_ELEMS;
    gating_kernel<<<T_TOKENS / 8, 256>>>(x, Wg, bg, logits, write_logits);

    scan_kernel<<<1, 1>>>();

#if defined(__CUDA_ARCH_SPECIFIC_LIST__)
    // arch-specific (sm_103a) build -> tcgen05 path
    cudaFuncSetAttribute(moe_gemm_tc<1>,
                         cudaFuncAttributeMaxDynamicSharedMemorySize, TC_SMEM_BYTES);
    cudaFuncSetAttribute(moe_gemm_tc<0>,
                         cudaFuncAttributeMaxDynamicSharedMemorySize, TC_SMEM_BYTES);
    dim3 g1(DF / 128, T_TOKENS / 128, N_EXP);
    moe_gemm_tc<1><<<g1, 256, TC_SMEM_BYTES>>>(x, W1, b1, nullptr);
    dim3 g2(DM / 128, T_TOKENS / 128, N_EXP);
    moe_gemm_tc<0><<<g2, 256, TC_SMEM_BYTES>>>(nullptr, W2, b2, out);
#else
    // non-specific build -> mma.sync tf32 pipelined fallback
    dim3 g1(DF / BN, T_TOKENS / BM, N_EXP);
    gemm1_fb<<<g1, 256>>>(x, W1, b1);
    dim3 g2(DM / BN, T_TOKENS / BM, N_EXP);
    gemm2_fb<<<g2, 256>>>(W2, b2, out);
#endif
}

// round 8
// speedup vs baseline: 1.2300x; 1.0287x over previous
#include <cuda_runtime.h>
#include <math.h>
#include <stdint.h>

#define T_TOKENS 8192
#define DM 1024
#define DF 4096
#define N_EXP 8

// ---------------- scratch (__device__ globals) ------------------------------
__device__ int   g_counts[N_EXP];
__device__ int   g_offsets[N_EXP];
__device__ int   g_tok[N_EXP * T_TOKENS];
__device__ float g_w[N_EXP * T_TOKENS];
__device__ float g_H[(size_t)16384 * DF];

// ---------------- helpers ----------------------------------------------------
__device__ __forceinline__ unsigned f2tf32(float f) {
    unsigned u;
    asm("cvt.rna.tf32.f32 %0, %1;" : "=r"(u) : "f"(f));
    return u;
}

__device__ __forceinline__ void mma_tf32(float c[4], const unsigned a[4], const unsigned b[2]) {
    asm volatile(
        "mma.sync.aligned.m16n8k8.row.col.f32.tf32.tf32.f32 "
        "{%0,%1,%2,%3}, {%4,%5,%6,%7}, {%8,%9}, {%0,%1,%2,%3};\n"
        : "+f"(c[0]), "+f"(c[1]), "+f"(c[2]), "+f"(c[3])
        : "r"(a[0]), "r"(a[1]), "r"(a[2]), "r"(a[3]), "r"(b[0]), "r"(b[1]));
}

__device__ __forceinline__ float gelu_exact(float v) {
    return 0.5f * v * (1.0f + erff(v * 0.70710678118654752f));
}

// ---------------- zero out + counters ----------------------------------------
__global__ void zero_kernel(float* __restrict__ out, int n4) {
    int i = blockIdx.x * blockDim.x + threadIdx.x;
    if (i < n4) reinterpret_cast<float4*>(out)[i] = make_float4(0.f, 0.f, 0.f, 0.f);
    if (i < N_EXP) g_counts[i] = 0;
}

// ---------------- gating: one warp per token ---------------------------------
__global__ void gating_kernel(const float* __restrict__ x,
                              const float* __restrict__ Wg,
                              const float* __restrict__ bg,
                              float* __restrict__ logits_out,
                              int write_logits) {
    int warp = threadIdx.x >> 5;
    int lane = threadIdx.x & 31;
    int t = blockIdx.x * (blockDim.x >> 5) + warp;
    if (t >= T_TOKENS) return;

    float acc[8];
#pragma unroll
    for (int e = 0; e < 8; e++) acc[e] = 0.f;

    const float4* x4 = reinterpret_cast<const float4*>(x + (size_t)t * DM);
#pragma unroll
    for (int j = 0; j < 8; j++) {
        int idx4 = j * 32 + lane;
        float4 v = x4[idx4];
        float vv[4] = {v.x, v.y, v.z, v.w};
        int i = idx4 * 4;
#pragma unroll
        for (int c = 0; c < 4; c++) {
            const float4* w4 = reinterpret_cast<const float4*>(Wg + (size_t)(i + c) * 8);
            float4 wa = w4[0], wb = w4[1];
            acc[0] += vv[c] * wa.x; acc[1] += vv[c] * wa.y;
            acc[2] += vv[c] * wa.z; acc[3] += vv[c] * wa.w;
            acc[4] += vv[c] * wb.x; acc[5] += vv[c] * wb.y;
            acc[6] += vv[c] * wb.z; acc[7] += vv[c] * wb.w;
        }
    }
#pragma unroll
    for (int e = 0; e < 8; e++)
#pragma unroll
        for (int o = 16; o > 0; o >>= 1)
            acc[e] += __shfl_xor_sync(0xffffffffu, acc[e], o);

    if (lane == 0) {
        float lg[8];
#pragma unroll
        for (int e = 0; e < 8; e++) lg[e] = acc[e] + bg[e];
        if (write_logits) {
#pragma unroll
            for (int e = 0; e < 8; e++) logits_out[(size_t)t * 8 + e] = lg[e];
        }
        float mx = lg[0];
#pragma unroll
        for (int e = 1; e < 8; e++) mx = fmaxf(mx, lg[e]);
        float p[8], s = 0.f;
#pragma unroll
        for (int e = 0; e < 8; e++) { p[e] = expf(lg[e] - mx); s += p[e]; }
        int i1 = 0;
#pragma unroll
        for (int e = 1; e < 8; e++) if (p[e] > p[i1]) i1 = e;
        int i2 = -1;
#pragma unroll
        for (int e = 0; e < 8; e++) {
            if (e == i1) continue;
            if (i2 < 0 || p[e] > p[i2]) i2 = e;
        }
        float w1 = p[i1] / s, w2 = p[i2] / s;
        int pos1 = atomicAdd(&g_counts[i1], 1);
        g_tok[i1 * T_TOKENS + pos1] = t;
        g_w[i1 * T_TOKENS + pos1] = w1;
        int pos2 = atomicAdd(&g_counts[i2], 1);
        g_tok[i2 * T_TOKENS + pos2] = t;
        g_w[i2 * T_TOKENS + pos2] = w2;
    }
}

__global__ void scan_kernel() {
    if (threadIdx.x == 0 && blockIdx.x == 0) {
        int s = 0;
        for (int e = 0; e < N_EXP; e++) { g_offsets[e] = s; s += g_counts[e]; }
    }
}

// ---------------- tiled tf32 GEMM: 128x128 CTA, 4 warps of 64x64 -------------
#define BM 128
#define BN 128
#define BK 16
#define SA 20    // A smem row stride (words) — conflict-free fragment loads
#define SB 136   // B smem row stride (words) — conflict-free fragment loads
#define NTHR 128

// IS_G1=1: A = x gathered by token, out = g_H (gelu+b1)
// IS_G1=0: A = g_H rows,          out = atomic combine into out (b2, weights)
template<int IS_G1>
__global__ __launch_bounds__(NTHR, 2) void moe_gemm_fb(
    const float* __restrict__ xin,
    const float* __restrict__ Wfull,
    const float* __restrict__ bias,
    float* __restrict__ out)
{
    constexpr int KTOT = IS_G1 ? DM : DF;
    constexpr int NTOT = IS_G1 ? DF : DM;

    int e = blockIdx.z;
    int cnt = g_counts[e];
    int m0 = blockIdx.y * BM;
    if (m0 >= cnt) return;
    int n0 = blockIdx.x * BN;
    int off = g_offsets[e];
    const float* W = Wfull + (size_t)e * KTOT * NTOT;
    const float* A = IS_G1 ? xin : g_H;

    __shared__ unsigned As[2][BM * SA];
    __shared__ unsigned Bs[2][BK * SB];

    int tid = threadIdx.x;
    int warp = tid >> 5, lane = tid & 31;
    int wm = (warp >> 1) * 64, wn = (warp & 1) * 64;
    int lr = lane >> 2, lc = lane & 3;

    // A-load rows: r = tid>>2 + h*32 for h = 0..3
    int rowv[4];
#pragma unroll
    for (int h = 0; h < 4; h++) {
        int r = (tid >> 2) + h * 32;
        int grow = m0 + r;
        if (grow >= cnt) rowv[h] = -1;
        else rowv[h] = IS_G1 ? g_tok[e * T_TOKENS + grow] : (off + grow);
    }

    float acc[4][8][4];
#pragma unroll
    for (int im = 0; im < 4; im++)
#pragma unroll
        for (int in_ = 0; in_ < 8; in_++)
#pragma unroll
            for (int q = 0; q < 4; q++) acc[im][in_][q] = 0.f;

    float4 va[4], vb[4];
    auto ldg = [&](int k0) {
#pragma unroll
        for (int h = 0; h < 4; h++) {
            int c = (tid & 3) * 4;
            va[h] = make_float4(0.f, 0.f, 0.f, 0.f);
            if (rowv[h] >= 0)
                va[h] = *reinterpret_cast<const float4*>(
                    A + (size_t)rowv[h] * KTOT + k0 + c);
        }
#pragma unroll
        for (int h = 0; h < 4; h++) {
            int idx = tid + h * NTHR;
            int k = idx >> 5, c = (idx & 31) * 4;
            vb[h] = *reinterpret_cast<const float4*>(
                W + (size_t)(k0 + k) * NTOT + n0 + c);
        }
    };
    auto sts = [&](int buf) {
#pragma unroll
        for (int h = 0; h < 4; h++) {
            int r = (tid >> 2) + h * 32;
            int c = (tid & 3) * 4;
            unsigned* dst = &As[buf][r * SA + c];
            dst[0] = f2tf32(va[h].x); dst[1] = f2tf32(va[h].y);
            dst[2] = f2tf32(va[h].z); dst[3] = f2tf32(va[h].w);
        }
#pragma unroll
        for (int h = 0; h < 4; h++) {
            int idx = tid + h * NTHR;
            int k = idx >> 5, c = (idx & 31) * 4;
            unsigned* dst = &Bs[buf][k * SB + c];
            dst[0] = f2tf32(vb[h].x); dst[1] = f2tf32(vb[h].y);
            dst[2] = f2tf32(vb[h].z); dst[3] = f2tf32(vb[h].w);
        }
    };

    ldg(0);
    sts(0);
    __syncthreads();

    const int nk = KTOT / BK;
    for (int kt = 0; kt < nk; kt++) {
        int buf = kt & 1;
        if (kt + 1 < nk) ldg((kt + 1) * BK);
#pragma unroll
        for (int ks = 0; ks < 2; ks++) {
            int kk = ks * 8;
            unsigned a[4][4], b[8][2];
#pragma unroll
            for (int im = 0; im < 4; im++) {
                int rb = wm + im * 16;
                a[im][0] = As[buf][(rb + lr) * SA + kk + lc];
                a[im][1] = As[buf][(rb + lr + 8) * SA + kk + lc];
                a[im][2] = As[buf][(rb + lr) * SA + kk + lc + 4];
                a[im][3] = As[buf][(rb + lr + 8) * SA + kk + lc + 4];
            }
#pragma unroll
            for (int in_ = 0; in_ < 8; in_++) {
                int nb = wn + in_ * 8 + lr;
                b[in_][0] = Bs[buf][(kk + lc) * SB + nb];
                b[in_][1] = Bs[buf][(kk + lc + 4) * SB + nb];
            }
#pragma unroll
            for (int im = 0; im < 4; im++)
#pragma unroll
                for (int in_ = 0; in_ < 8; in_++)
                    mma_tf32(acc[im][in_], a[im], b[in_]);
        }
        if (kt + 1 < nk) sts(buf ^ 1);
        __syncthreads();
    }

    // ---- epilogue ----
#pragma unroll
    for (int im = 0; im < 4; im++) {
#pragma unroll
        for (int in_ = 0; in_ < 8; in_++) {
            int col = n0 + wn + in_ * 8 + lc * 2;
            float bias0 = bias[(size_t)e * NTOT + col];
            float bias1 = bias[(size_t)e * NTOT + col + 1];
#pragma unroll
            for (int half = 0; half < 2; half++) {
                int r = wm + im * 16 + lr + half * 8;
                int grow = m0 + r;
                if (grow < cnt) {
                    float v0 = acc[im][in_][half * 2 + 0] + bias0;
                    float v1 = acc[im][in_][half * 2 + 1] + bias1;
                    if (IS_G1) {
                        size_t hrow = (size_t)(off + grow);
                        g_H[hrow * DF + col] = gelu_exact(v0);
                        g_H[hrow * DF + col + 1] = gelu_exact(v1);
                    } else {
                        int tok = g_tok[e * T_TOKENS + grow];
                        float w = g_w[e * T_TOKENS + grow];
                        atomicAdd(&out[(size_t)tok * DM + col], w * v0);
                        atomicAdd(&out[(size_t)tok * DM + col + 1], w * v1);
                    }
                }
            }
        }
    }
}

// ---------------- launch -----------------------------------------------------
extern "C" void kernel_launch(void* const* d_in, const int* in_sizes, int n_in,
                              void* d_out, int out_size) {
    const float* x  = (const float*)d_in[0];
    const float* Wg = (const float*)d_in[1];
    const float* bg = (const float*)d_in[2];
    const float* W1 = (const float*)d_in[3];
    const float* b1 = (const float*)d_in[4];
    const float* W2 = (const float*)d_in[5];
    const float* b2 = (const float*)d_in[6];
    float* out = (float*)d_out;

    int n4 = out_size / 4;
    zero_kernel<<<(n4 + 255) / 256, 256>>>(out, n4);

    const int OUT_ELEMS = T_TOKENS * DM;
    int write_logits = (out_size >= OUT_ELEMS + T_TOKENS * N_EXP);
    float* logits = out + OUT_ELEMS;
    gating_kernel<<<T_TOKENS / 8, 256>>>(x, Wg, bg, logits, write_logits);

    scan_kernel<<<1, 1>>>();

    dim3 g1(DF / BN, T_TOKENS / BM, N_EXP);
    moe_gemm_fb<1><<<g1, NTHR>>>(x, W1, b1, nullptr);

    dim3 g2(DM / BN, T_TOKENS / BM, N_EXP);
    moe_gemm_fb<0><<<g2, NTHR>>>(nullptr, W2, b2, out);
}